// round 5
// baseline (speedup 1.0000x reference)
#include <cuda_runtime.h>
#include <cuda_bf16.h>
#include <cstdint>

#define EE   2048
#define CC   64
#define FF   18
#define NSTG 32      // K stages of 64 in main GEMM
#define KS   64

typedef unsigned long long u64;
typedef unsigned int u32;

// Scratch (__device__ globals: allocation-free rule)
__device__ float g_T1[CC * EE];                           // Wmp @ Wo
__device__ float g_u[EE];                                 // bv @ Wo^T + bo
__device__ __align__(16) float g_beta[CC];
__device__ __align__(16) unsigned char g_Bh[CC * EE * 2]; // M hi, pre-swizzled per-stage tiles
__device__ __align__(16) unsigned char g_Bl[CC * EE * 2]; // M lo, pre-swizzled per-stage tiles

// ---------------- helpers ----------------
__device__ __forceinline__ unsigned smem_u32(const void* p) {
    return (unsigned)__cvta_generic_to_shared(p);
}
__device__ __forceinline__ void cp16(unsigned s, const void* g) {
    asm volatile("cp.async.ca.shared.global [%0], [%1], 16;" :: "r"(s), "l"(g));
}
__device__ __forceinline__ void cp_commit() { asm volatile("cp.async.commit_group;"); }
__device__ __forceinline__ void cp_wait0()  { asm volatile("cp.async.wait_group 0;"); }
__device__ __forceinline__ void sts64(u32 a, u32 lo, u32 hi) {
    asm volatile("st.shared.v2.u32 [%0], {%1,%2};" :: "r"(a), "r"(lo), "r"(hi));
}
__device__ __forceinline__ void ldsm4(u32& r0, u32& r1, u32& r2, u32& r3, u32 a) {
    asm volatile("ldmatrix.sync.aligned.m8n8.x4.shared.b16 {%0,%1,%2,%3}, [%4];"
                 : "=r"(r0), "=r"(r1), "=r"(r2), "=r"(r3) : "r"(a));
}
__device__ __forceinline__ void ldsm4t(u32& r0, u32& r1, u32& r2, u32& r3, u32 a) {
    asm volatile("ldmatrix.sync.aligned.m8n8.x4.trans.shared.b16 {%0,%1,%2,%3}, [%4];"
                 : "=r"(r0), "=r"(r1), "=r"(r2), "=r"(r3) : "r"(a));
}
__device__ __forceinline__ void mma16816(float* c, u32 a0, u32 a1, u32 a2, u32 a3,
                                         u32 b0, u32 b1) {
    asm volatile("mma.sync.aligned.m16n8k16.row.col.f32.bf16.bf16.f32 "
                 "{%0,%1,%2,%3}, {%4,%5,%6,%7}, {%8,%9}, {%0,%1,%2,%3};"
                 : "+f"(c[0]), "+f"(c[1]), "+f"(c[2]), "+f"(c[3])
                 : "r"(a0), "r"(a1), "r"(a2), "r"(a3), "r"(b0), "r"(b1));
}
__device__ __forceinline__ u32 swz(u32 off) { return off ^ ((off >> 3) & 0x70u); }

// convert float4 -> bf16 hi pair-regs + lo pair-regs
__device__ __forceinline__ void split4(float4 v, u32& h01, u32& h23, u32& l01, u32& l23) {
    asm("cvt.rn.bf16x2.f32 %0, %1, %2;" : "=r"(h01) : "f"(v.y), "f"(v.x));
    asm("cvt.rn.bf16x2.f32 %0, %1, %2;" : "=r"(h23) : "f"(v.w), "f"(v.z));
    float e0 = v.x - __uint_as_float(h01 << 16);
    float e1 = v.y - __uint_as_float(h01 & 0xffff0000u);
    float e2 = v.z - __uint_as_float(h23 << 16);
    float e3 = v.w - __uint_as_float(h23 & 0xffff0000u);
    asm("cvt.rn.bf16x2.f32 %0, %1, %2;" : "=r"(l01) : "f"(e1), "f"(e0));
    asm("cvt.rn.bf16x2.f32 %0, %1, %2;" : "=r"(l23) : "f"(e3), "f"(e2));
}

// ---------------------------------------------------------------------------
// wgemm: D[64, 2048] = A[64x2048] @ B[2048x2048]  (both row-major fp32)
// 3-term bf16 split on tensor cores. Full K per CTA (no partials).
// grid = 32 j-tiles of 64. mode 0: D -> g_T1 (fp32).
// mode 1: 0.75*D -> g_Bh/g_Bl (bf16 hi/lo, pre-swizzled per-stage tiles).
// ---------------------------------------------------------------------------
__global__ void __launch_bounds__(256, 1)
wgemm(const float* __restrict__ Aglob, const float* __restrict__ Bglob,
      int useT1, int mode)
{
    const float* A = useT1 ? g_T1 : Aglob;
    __shared__ __align__(16) unsigned char sm[32768];
    const u32 AH = smem_u32(sm);
    const u32 AL = AH + 8192, BSH = AH + 16384, BSL = AH + 24576;

    const int tid = threadIdx.x;
    const int wid = tid >> 5, lane = tid & 31;
    const int j0 = blockIdx.x * 64;
    const int c0 = (wid & 3) * 16;       // m-slice
    const int jh = (wid >> 2) * 32;      // n-half within tile

    const int lr = tid >> 4;             // row base 0..15
    const int lc = tid & 15;             // float4 col

    float acc[4][4];
#pragma unroll
    for (int i = 0; i < 4; ++i)
#pragma unroll
        for (int j = 0; j < 4; ++j) acc[i][j] = 0.f;

    // prefetch chunk 0
    float4 rA[4], rB[4];
#pragma unroll
    for (int i = 0; i < 4; ++i) {
        rA[i] = *(const float4*)(A + (size_t)(lr + 16 * i) * EE + lc * 4);
        rB[i] = *(const float4*)(Bglob + (size_t)(lr + 16 * i) * EE + j0 + lc * 4);
    }

    for (int t = 0; t < 32; ++t) {
        if (t) __syncthreads();          // protect smem from previous MMA readers

        // convert & store chunk t (A: [c][k] rows 128B; B: [k][j] rows 128B)
#pragma unroll
        for (int i = 0; i < 4; ++i) {
            const u32 sw = swz((u32)((lr + 16 * i) * 128 + lc * 8));
            u32 h01, h23, l01, l23;
            split4(rA[i], h01, h23, l01, l23);
            sts64(AH + sw, h01, h23);
            sts64(AL + sw, l01, l23);
            split4(rB[i], h01, h23, l01, l23);
            sts64(BSH + sw, h01, h23);
            sts64(BSL + sw, l01, l23);
        }
        __syncthreads();

        // prefetch chunk t+1 (overlaps with MMA below)
        if (t + 1 < 32) {
            const int kc = (t + 1) * 64;
#pragma unroll
            for (int i = 0; i < 4; ++i) {
                rA[i] = *(const float4*)(A + (size_t)(lr + 16 * i) * EE + kc + lc * 4);
                rB[i] = *(const float4*)(Bglob + (size_t)(kc + lr + 16 * i) * EE + j0 + lc * 4);
            }
        }

        // MMA chunk t: warp does m16 x n32 x k64, 3 terms
        const int r = lane & 7, g = lane >> 3;
#pragma unroll
        for (int s = 0; s < 4; ++s) {
            const u32 asw = swz((u32)((c0 + (lane & 15)) * 128 + s * 32 + (lane >> 4) * 16));
            u32 a0, a1, a2, a3, f0, f1, f2, f3;
            ldsm4(a0, a1, a2, a3, AH + asw);
            ldsm4(f0, f1, f2, f3, AL + asw);
#pragma unroll
            for (int h = 0; h < 2; ++h) {
                const int jb = jh + h * 16;
                const u32 bsw = swz((u32)((s * 16 + (g >> 1) * 8 + r) * 128
                                          + (jb + (g & 1) * 8) * 2));
                u32 b0, b1, b2, b3, e0, e1, e2, e3;
                ldsm4t(b0, b1, b2, b3, BSH + bsw);
                ldsm4t(e0, e1, e2, e3, BSL + bsw);
                mma16816(acc[2 * h],     a0, a1, a2, a3, b0, b2);
                mma16816(acc[2 * h],     a0, a1, a2, a3, e0, e2);
                mma16816(acc[2 * h],     f0, f1, f2, f3, b0, b2);
                mma16816(acc[2 * h + 1], a0, a1, a2, a3, b1, b3);
                mma16816(acc[2 * h + 1], a0, a1, a2, a3, e1, e3);
                mma16816(acc[2 * h + 1], f0, f1, f2, f3, b1, b3);
            }
        }
    }

    // Epilogue
    const int r0 = lane >> 2;            // 0..7
    const int cb = 2 * (lane & 3);       // col pair within n8
#pragma unroll
    for (int nt = 0; nt < 4; ++nt) {
        const int j = j0 + jh + nt * 8 + cb;       // even
        const int ca = c0 + r0, cbig = ca + 8;
        if (mode == 0) {
            *(float2*)&g_T1[(size_t)ca * EE + j]   = make_float2(acc[nt][0], acc[nt][1]);
            *(float2*)&g_T1[(size_t)cbig * EE + j] = make_float2(acc[nt][2], acc[nt][3]);
        } else {
            const int stage = j >> 6, kk = j & 63;
#pragma unroll
            for (int half = 0; half < 2; ++half) {
                const int c = half ? cbig : ca;
                float v0 = 0.75f * acc[nt][2 * half];
                float v1 = 0.75f * acc[nt][2 * half + 1];
                u32 hp, lp;
                asm("cvt.rn.bf16x2.f32 %0, %1, %2;" : "=r"(hp) : "f"(v1), "f"(v0));
                float e0 = v0 - __uint_as_float(hp << 16);
                float e1 = v1 - __uint_as_float(hp & 0xffff0000u);
                asm("cvt.rn.bf16x2.f32 %0, %1, %2;" : "=r"(lp) : "f"(e1), "f"(e0));
                const u32 sw = swz((u32)(c * 128 + kk * 2));
                *(u32*)(g_Bh + (size_t)stage * 8192 + sw) = hp;
                *(u32*)(g_Bl + (size_t)stage * 8192 + sw) = lp;
            }
        }
    }
}

// u[i] = sum_j bv[j]*Wo[i,j] + bo[i]
__global__ void k_u(const float* __restrict__ bv, const float* __restrict__ Wo,
                    const float* __restrict__ bo)
{
    const int w = (blockIdx.x * 256 + threadIdx.x) >> 5;
    const int lane = threadIdx.x & 31;
    const float* row = Wo + (size_t)w * EE;
    float s = 0.f;
    for (int j = lane; j < EE; j += 32) s += bv[j] * row[j];
#pragma unroll
    for (int o = 16; o; o >>= 1) s += __shfl_xor_sync(0xffffffffu, s, o);
    if (lane == 0) g_u[w] = s + bo[w];
}

// beta[c] = 0.75 * sum_i u[i]*Wmp[c,i] + bmp[c]
__global__ void k_beta(const float* __restrict__ Wmp, const float* __restrict__ bmp)
{
    const int c = blockIdx.x;
    const int lane = threadIdx.x;
    const float* row = Wmp + (size_t)c * EE;
    float s = 0.f;
    for (int i = lane; i < EE; i += 32) s += g_u[i] * row[i];
#pragma unroll
    for (int o = 16; o; o >>= 1) s += __shfl_xor_sync(0xffffffffu, s, o);
    if (lane == 0) g_beta[c] = 0.75f * s + bmp[c];
}

// ---------------------------------------------------------------------------
// Main GEMM via mma.sync bf16 split:  out[n,c] = x[n,:] . M[c,:] + beta[c]
//   D += Ah*Bh + Ah*Bl + Al*Bh  (fp32 register accumulators)
// 144 CTAs x 256 threads (8 warps x m16). K in 32 chunks of 64, double-buffered.
// ---------------------------------------------------------------------------
__global__ void __launch_bounds__(256, 1)
main_mma(const float* __restrict__ x, float* __restrict__ out)
{
    extern __shared__ char smraw[];
    const u32 base = (smem_u32(smraw) + 1023u) & ~1023u;
    const u32 XH[2] = { base,          base + 16384u };
    const u32 XL[2] = { base + 32768u, base + 49152u };
    const u32 BH[2] = { base + 65536u, base + 73728u };
    const u32 BL[2] = { base + 81920u, base + 90112u };

    const int tid = threadIdx.x;
    const int wid = tid >> 5, lane = tid & 31;
    const int n0 = blockIdx.x * 128;
    const int m0 = wid * 16;

    float acc[8][4];
#pragma unroll
    for (int i = 0; i < 8; ++i)
#pragma unroll
        for (int j = 0; j < 4; ++j) acc[i][j] = 0.f;

    const int xr = tid >> 4, xc4 = tid & 15;

    // prologue: chunk 0
    float4 ra[8];
#pragma unroll
    for (int i = 0; i < 8; ++i)
        ra[i] = *(const float4*)(x + (size_t)(n0 + xr + 16 * i) * EE + xc4 * 4);
    {
        const char* sh = (const char*)g_Bh + (size_t)tid * 32;
        const char* sl = (const char*)g_Bl + (size_t)tid * 32;
        cp16(BH[0] + (u32)tid * 32,      sh);
        cp16(BH[0] + (u32)tid * 32 + 16, sh + 16);
        cp16(BL[0] + (u32)tid * 32,      sl);
        cp16(BL[0] + (u32)tid * 32 + 16, sl + 16);
        cp_commit();
    }

    for (int t = 0; t < NSTG; ++t) {
        const int buf = t & 1;
        cp_wait0();

        // convert & store X chunk t (hi/lo, swizzled)
#pragma unroll
        for (int i = 0; i < 8; ++i) {
            const u32 sw = swz((u32)((xr + 16 * i) * 128 + xc4 * 8));
            u32 h01, h23, l01, l23;
            split4(ra[i], h01, h23, l01, l23);
            sts64(XH[buf] + sw, h01, h23);
            sts64(XL[buf] + sw, l01, l23);
        }
        __syncthreads();

        // issue next-chunk B cp.async + X LDG prefetch (overlap with MMA)
        if (t + 1 < NSTG) {
            const u32 nb = BH[buf ^ 1], nl = BL[buf ^ 1];
            const char* sh = (const char*)g_Bh + (size_t)(t + 1) * 8192 + tid * 32;
            const char* sl = (const char*)g_Bl + (size_t)(t + 1) * 8192 + tid * 32;
            cp16(nb + (u32)tid * 32,      sh);
            cp16(nb + (u32)tid * 32 + 16, sh + 16);
            cp16(nl + (u32)tid * 32,      sl);
            cp16(nl + (u32)tid * 32 + 16, sl + 16);
            cp_commit();
            const int k0 = (t + 1) * KS;
#pragma unroll
            for (int i = 0; i < 8; ++i)
                ra[i] = *(const float4*)(x + (size_t)(n0 + xr + 16 * i) * EE + k0 + xc4 * 4);
        }

        // MMA over chunk t
#pragma unroll
        for (int s = 0; s < 4; ++s) {
            const u32 xo = swz((u32)((m0 + (lane & 15)) * 128 + s * 32 + (lane >> 4) * 16));
            u32 a0, a1, a2, a3, f0, f1, f2, f3;
            ldsm4(a0, a1, a2, a3, XH[buf] + xo);
            ldsm4(f0, f1, f2, f3, XL[buf] + xo);
#pragma unroll
            for (int j = 0; j < 4; ++j) {
                const u32 bo = swz((u32)((16 * j + (lane & 15)) * 128 + s * 32 + (lane >> 4) * 16));
                u32 h0, h1, h2, h3, l0, l1, l2, l3;
                ldsm4(h0, h1, h2, h3, BH[buf] + bo);
                ldsm4(l0, l1, l2, l3, BL[buf] + bo);
                mma16816(acc[2 * j],     a0, a1, a2, a3, h0, h2);
                mma16816(acc[2 * j],     a0, a1, a2, a3, l0, l2);
                mma16816(acc[2 * j],     f0, f1, f2, f3, h0, h2);
                mma16816(acc[2 * j + 1], a0, a1, a2, a3, h1, h3);
                mma16816(acc[2 * j + 1], a0, a1, a2, a3, l1, l3);
                mma16816(acc[2 * j + 1], f0, f1, f2, f3, h1, h3);
            }
        }
    }

    // Epilogue: permuted store [F,P]->[P,F], + beta
    const int r0 = lane >> 2;
    const int cb = 2 * (lane & 3);
    const int na = n0 + m0 + r0;
    const int nb2 = na + 8;
    const int pa = na & 1023, ta = na >> 10;
    const int pb = nb2 & 1023, tb = nb2 >> 10;
    float* oa = out + (size_t)pa * (FF * CC) + ta * CC;
    float* ob = out + (size_t)pb * (FF * CC) + tb * CC;
#pragma unroll
    for (int nt = 0; nt < 8; ++nt) {
        const int c = 8 * nt + cb;
        const float2 b = *(const float2*)&g_beta[c];
        float2 w0, w1;
        w0.x = acc[nt][0] + b.x; w0.y = acc[nt][1] + b.y;
        w1.x = acc[nt][2] + b.x; w1.y = acc[nt][3] + b.y;
        *(float2*)(oa + c) = w0;
        *(float2*)(ob + c) = w1;
    }
}

// ---------------------------------------------------------------------------
extern "C" void kernel_launch(void* const* d_in, const int* in_sizes, int n_in,
                              void* d_out, int out_size)
{
    (void)in_sizes; (void)n_in; (void)out_size;
    const float* emb = (const float*)d_in[0];
    const float* Wv  = (const float*)d_in[3];
    const float* bv  = (const float*)d_in[6];
    const float* Wo  = (const float*)d_in[7];
    const float* bo  = (const float*)d_in[8];
    const float* Wmp = (const float*)d_in[9];
    const float* bmp = (const float*)d_in[10];
    float* out = (float*)d_out;

    // Fold weights on tensor cores:
    //   T1 = Wmp @ Wo  (fp32 out) ; M = 0.75 * T1 @ Wv (split bf16 hi/lo, pre-swizzled)
    wgemm<<<32, 256>>>(Wmp, Wo, 0, 0);
    wgemm<<<32, 256>>>(nullptr, Wv, 1, 1);

    // Fold biases: beta = 0.75*(bv@Wo^T + bo)@Wmp^T + bmp
    k_u<<<256, 256>>>(bv, Wo, bo);
    k_beta<<<64, 32>>>(Wmp, bmp);

    // Main GEMM (HMMA bf16 3-term split) + permuted epilogue
    const int smem_bytes = 98304 + 1024;
    cudaFuncSetAttribute(main_mma, cudaFuncAttributeMaxDynamicSharedMemorySize, smem_bytes);
    main_mma<<<144, 256, smem_bytes>>>(emb, out);
}

// round 6
// speedup vs baseline: 1.0262x; 1.0262x over previous
#include <cuda_runtime.h>
#include <cuda_bf16.h>
#include <cstdint>

#define EE   2048
#define CC   64
#define FF   18
#define NSTG 32      // K stages of 64 in main GEMM
#define KS   64

typedef unsigned long long u64;
typedef unsigned int u32;

// Scratch (__device__ globals: allocation-free rule)
__device__ float g_T1[CC * EE];                           // Wmp @ Wo
__device__ __align__(16) float g_beta[CC];
__device__ __align__(16) unsigned char g_Bh[CC * EE * 2]; // M hi, pre-swizzled per-stage tiles
__device__ __align__(16) unsigned char g_Bl[CC * EE * 2]; // M lo, pre-swizzled per-stage tiles

// ---------------- helpers ----------------
__device__ __forceinline__ unsigned smem_u32(const void* p) {
    return (unsigned)__cvta_generic_to_shared(p);
}
__device__ __forceinline__ void cp16(unsigned s, const void* g) {
    asm volatile("cp.async.ca.shared.global [%0], [%1], 16;" :: "r"(s), "l"(g));
}
__device__ __forceinline__ void cp_commit() { asm volatile("cp.async.commit_group;"); }
template <int N>
__device__ __forceinline__ void cp_wait() { asm volatile("cp.async.wait_group %0;" :: "n"(N)); }
__device__ __forceinline__ void sts64(u32 a, u32 lo, u32 hi) {
    asm volatile("st.shared.v2.u32 [%0], {%1,%2};" :: "r"(a), "r"(lo), "r"(hi));
}
__device__ __forceinline__ void ldsm4(u32& r0, u32& r1, u32& r2, u32& r3, u32 a) {
    asm volatile("ldmatrix.sync.aligned.m8n8.x4.shared.b16 {%0,%1,%2,%3}, [%4];"
                 : "=r"(r0), "=r"(r1), "=r"(r2), "=r"(r3) : "r"(a));
}
__device__ __forceinline__ void ldsm4t(u32& r0, u32& r1, u32& r2, u32& r3, u32 a) {
    asm volatile("ldmatrix.sync.aligned.m8n8.x4.trans.shared.b16 {%0,%1,%2,%3}, [%4];"
                 : "=r"(r0), "=r"(r1), "=r"(r2), "=r"(r3) : "r"(a));
}
__device__ __forceinline__ void mma16816(float* c, u32 a0, u32 a1, u32 a2, u32 a3,
                                         u32 b0, u32 b1) {
    asm volatile("mma.sync.aligned.m16n8k16.row.col.f32.bf16.bf16.f32 "
                 "{%0,%1,%2,%3}, {%4,%5,%6,%7}, {%8,%9}, {%0,%1,%2,%3};"
                 : "+f"(c[0]), "+f"(c[1]), "+f"(c[2]), "+f"(c[3])
                 : "r"(a0), "r"(a1), "r"(a2), "r"(a3), "r"(b0), "r"(b1));
}
__device__ __forceinline__ u32 swz(u32 off) { return off ^ ((off >> 3) & 0x70u); }

// convert float4 -> bf16 hi pair-regs + lo pair-regs
__device__ __forceinline__ void split4(float4 v, u32& h01, u32& h23, u32& l01, u32& l23) {
    asm("cvt.rn.bf16x2.f32 %0, %1, %2;" : "=r"(h01) : "f"(v.y), "f"(v.x));
    asm("cvt.rn.bf16x2.f32 %0, %1, %2;" : "=r"(h23) : "f"(v.w), "f"(v.z));
    float e0 = v.x - __uint_as_float(h01 << 16);
    float e1 = v.y - __uint_as_float(h01 & 0xffff0000u);
    float e2 = v.z - __uint_as_float(h23 << 16);
    float e3 = v.w - __uint_as_float(h23 & 0xffff0000u);
    asm("cvt.rn.bf16x2.f32 %0, %1, %2;" : "=r"(l01) : "f"(e1), "f"(e0));
    asm("cvt.rn.bf16x2.f32 %0, %1, %2;" : "=r"(l23) : "f"(e3), "f"(e2));
}

// ---------------------------------------------------------------------------
// wgemm: D[64, 2048] = A[64x2048] @ B[2048x2048]  (both row-major fp32)
// 3-term bf16 split on tensor cores. Full K per CTA. Double-buffered smem.
// grid = 32 j-tiles of 64 (+1 beta block in mode 1).
// mode 0: D -> g_T1 (fp32).
// mode 1: 0.75*D -> g_Bh/g_Bl (bf16 hi/lo, pre-swizzled per-stage tiles),
//         and blockIdx.x==32 computes g_beta = 0.75*(T1@bv + Wmp@bo) + bmp.
// ---------------------------------------------------------------------------
__global__ void __launch_bounds__(256, 1)
wgemm(const float* __restrict__ Aglob, const float* __restrict__ Bglob,
      int useT1, int mode,
      const float* __restrict__ bv, const float* __restrict__ bo,
      const float* __restrict__ bmp, const float* __restrict__ WmpB)
{
    const int tid = threadIdx.x;
    const int wid = tid >> 5, lane = tid & 31;

    // ---- beta block (mode 1 only) ----
    if (mode && blockIdx.x == 32) {
#pragma unroll
        for (int q = 0; q < 8; ++q) {
            const int c = wid * 8 + q;
            const float* t1r = g_T1 + (size_t)c * EE;
            const float* wmr = WmpB + (size_t)c * EE;
            float s = 0.f;
            for (int k = lane; k < EE; k += 32)
                s += t1r[k] * bv[k] + wmr[k] * bo[k];
#pragma unroll
            for (int o = 16; o; o >>= 1) s += __shfl_xor_sync(0xffffffffu, s, o);
            if (lane == 0) g_beta[c] = 0.75f * s + bmp[c];
        }
        return;
    }

    const float* A = useT1 ? g_T1 : Aglob;
    extern __shared__ char smraw[];
    const u32 base = (smem_u32(smraw) + 1023u) & ~1023u;
    const u32 AH[2]  = { base,          base + 8192u  };
    const u32 AL[2]  = { base + 16384u, base + 24576u };
    const u32 BSH[2] = { base + 32768u, base + 40960u };
    const u32 BSL[2] = { base + 49152u, base + 57344u };

    const int j0 = blockIdx.x * 64;
    const int c0 = (wid & 3) * 16;       // m-slice
    const int jh = (wid >> 2) * 32;      // n-half within tile

    const int lr = tid >> 4;             // row base 0..15
    const int lc = tid & 15;             // float4 col

    float acc[4][4];
#pragma unroll
    for (int i = 0; i < 4; ++i)
#pragma unroll
        for (int j = 0; j < 4; ++j) acc[i][j] = 0.f;

    // prefetch chunk 0
    float4 rA[4], rB[4];
#pragma unroll
    for (int i = 0; i < 4; ++i) {
        rA[i] = *(const float4*)(A + (size_t)(lr + 16 * i) * EE + lc * 4);
        rB[i] = *(const float4*)(Bglob + (size_t)(lr + 16 * i) * EE + j0 + lc * 4);
    }

    for (int t = 0; t < 32; ++t) {
        const int buf = t & 1;

        // store chunk t into buf (other buffer is being read by nobody now;
        // single sync per stage is safe: see hazard analysis in commit msg)
#pragma unroll
        for (int i = 0; i < 4; ++i) {
            const u32 sw = swz((u32)((lr + 16 * i) * 128 + lc * 8));
            u32 h01, h23, l01, l23;
            split4(rA[i], h01, h23, l01, l23);
            sts64(AH[buf] + sw, h01, h23);
            sts64(AL[buf] + sw, l01, l23);
            split4(rB[i], h01, h23, l01, l23);
            sts64(BSH[buf] + sw, h01, h23);
            sts64(BSL[buf] + sw, l01, l23);
        }
        __syncthreads();

        // prefetch chunk t+1 (overlaps with MMA below)
        if (t + 1 < 32) {
            const int kc = (t + 1) * 64;
#pragma unroll
            for (int i = 0; i < 4; ++i) {
                rA[i] = *(const float4*)(A + (size_t)(lr + 16 * i) * EE + kc + lc * 4);
                rB[i] = *(const float4*)(Bglob + (size_t)(kc + lr + 16 * i) * EE + j0 + lc * 4);
            }
        }

        // MMA chunk t: warp does m16 x n32 x k64, 3 terms
        const int r = lane & 7, g = lane >> 3;
#pragma unroll
        for (int s = 0; s < 4; ++s) {
            const u32 asw = swz((u32)((c0 + (lane & 15)) * 128 + s * 32 + (lane >> 4) * 16));
            u32 a0, a1, a2, a3, f0, f1, f2, f3;
            ldsm4(a0, a1, a2, a3, AH[buf] + asw);
            ldsm4(f0, f1, f2, f3, AL[buf] + asw);
#pragma unroll
            for (int h = 0; h < 2; ++h) {
                const int jb = jh + h * 16;
                const u32 bsw = swz((u32)((s * 16 + (g >> 1) * 8 + r) * 128
                                          + (jb + (g & 1) * 8) * 2));
                u32 b0, b1, b2, b3, e0, e1, e2, e3;
                ldsm4t(b0, b1, b2, b3, BSH[buf] + bsw);
                ldsm4t(e0, e1, e2, e3, BSL[buf] + bsw);
                mma16816(acc[2 * h],     a0, a1, a2, a3, b0, b2);
                mma16816(acc[2 * h],     a0, a1, a2, a3, e0, e2);
                mma16816(acc[2 * h],     f0, f1, f2, f3, b0, b2);
                mma16816(acc[2 * h + 1], a0, a1, a2, a3, b1, b3);
                mma16816(acc[2 * h + 1], a0, a1, a2, a3, e1, e3);
                mma16816(acc[2 * h + 1], f0, f1, f2, f3, b1, b3);
            }
        }
    }

    // Epilogue
    const int r0 = lane >> 2;            // 0..7
    const int cb = 2 * (lane & 3);       // col pair within n8
#pragma unroll
    for (int nt = 0; nt < 4; ++nt) {
        const int j = j0 + jh + nt * 8 + cb;
        const int ca = c0 + r0, cbig = ca + 8;
        if (mode == 0) {
            *(float2*)&g_T1[(size_t)ca * EE + j]   = make_float2(acc[nt][0], acc[nt][1]);
            *(float2*)&g_T1[(size_t)cbig * EE + j] = make_float2(acc[nt][2], acc[nt][3]);
        } else {
            const int stage = j >> 6, kk = j & 63;
#pragma unroll
            for (int half = 0; half < 2; ++half) {
                const int c = half ? cbig : ca;
                float v0 = 0.75f * acc[nt][2 * half];
                float v1 = 0.75f * acc[nt][2 * half + 1];
                u32 hp, lp;
                asm("cvt.rn.bf16x2.f32 %0, %1, %2;" : "=r"(hp) : "f"(v1), "f"(v0));
                float e0 = v0 - __uint_as_float(hp << 16);
                float e1 = v1 - __uint_as_float(hp & 0xffff0000u);
                asm("cvt.rn.bf16x2.f32 %0, %1, %2;" : "=r"(lp) : "f"(e1), "f"(e0));
                const u32 sw = swz((u32)(c * 128 + kk * 2));
                *(u32*)(g_Bh + (size_t)stage * 8192 + sw) = hp;
                *(u32*)(g_Bl + (size_t)stage * 8192 + sw) = lp;
            }
        }
    }
}

// ---------------------------------------------------------------------------
// Main GEMM via mma.sync bf16 split:  out[n,c] = x[n,:] . M[c,:] + beta[c]
//   D += Ah*Bh + Ah*Bl + Al*Bh  (fp32 register accumulators)
// 288 CTAs x 128 threads (4 warps x m16 = 64-token tile) -> 2 CTAs/SM so an
// independent CTA fills sync/wait bubbles. B: 3-slot cp.async pipeline
// (wait_group 1, two groups in flight). X: register prefetch distance 1,
// converted fp32->bf16 hi/lo in-kernel. Permuted [F,P]->[P,F] epilogue.
// ---------------------------------------------------------------------------
__global__ void __launch_bounds__(128, 2)
main_mma(const float* __restrict__ x, float* __restrict__ out)
{
    extern __shared__ char smraw[];
    const u32 base = (smem_u32(smraw) + 1023u) & ~1023u;
    const u32 XH[2] = { base,          base + 8192u };
    const u32 XL[2] = { base + 16384u, base + 24576u };
    const u32 BH[3] = { base + 32768u, base + 40960u, base + 49152u };
    const u32 BL[3] = { base + 57344u, base + 65536u, base + 73728u };

    const int tid = threadIdx.x;
    const int wid = tid >> 5, lane = tid & 31;
    const int n0 = blockIdx.x * 64;
    const int m0 = wid * 16;

    float acc[8][4];
#pragma unroll
    for (int i = 0; i < 8; ++i)
#pragma unroll
        for (int j = 0; j < 4; ++j) acc[i][j] = 0.f;

    const int xr = tid >> 4, xc4 = tid & 15;   // rows xr+8i, float4-col xc4

    // prologue: X chunk 0 regs; B chunks 0 and 1 in flight
    float4 ra[8];
#pragma unroll
    for (int i = 0; i < 8; ++i)
        ra[i] = *(const float4*)(x + (size_t)(n0 + xr + 8 * i) * EE + xc4 * 4);
#pragma unroll
    for (int pb = 0; pb < 2; ++pb) {
        const char* sh = (const char*)g_Bh + (size_t)pb * 8192 + tid * 64;
        const char* sl = (const char*)g_Bl + (size_t)pb * 8192 + tid * 64;
#pragma unroll
        for (int q = 0; q < 4; ++q) {
            cp16(BH[pb] + (u32)tid * 64 + q * 16, sh + q * 16);
            cp16(BL[pb] + (u32)tid * 64 + q * 16, sl + q * 16);
        }
        cp_commit();
    }

    for (int t = 0; t < NSTG; ++t) {
        const int buf = t & 1;
        const int bslot = t % 3;

        if (t + 1 < NSTG) cp_wait<1>(); else cp_wait<0>();   // B chunk t arrived

        // convert & store X chunk t (hi/lo, swizzled)
#pragma unroll
        for (int i = 0; i < 8; ++i) {
            const u32 sw = swz((u32)((xr + 8 * i) * 128 + xc4 * 8));
            u32 h01, h23, l01, l23;
            split4(ra[i], h01, h23, l01, l23);
            sts64(XH[buf] + sw, h01, h23);
            sts64(XL[buf] + sw, l01, l23);
        }
        __syncthreads();

        // issue B chunk t+2 + X chunk t+1 LDG prefetch (overlap with MMA)
        if (t + 2 < NSTG) {
            const int ns = (t + 2) % 3;
            const char* sh = (const char*)g_Bh + (size_t)(t + 2) * 8192 + tid * 64;
            const char* sl = (const char*)g_Bl + (size_t)(t + 2) * 8192 + tid * 64;
#pragma unroll
            for (int q = 0; q < 4; ++q) {
                cp16(BH[ns] + (u32)tid * 64 + q * 16, sh + q * 16);
                cp16(BL[ns] + (u32)tid * 64 + q * 16, sl + q * 16);
            }
            cp_commit();
        }
        if (t + 1 < NSTG) {
            const int k0 = (t + 1) * KS;
#pragma unroll
            for (int i = 0; i < 8; ++i)
                ra[i] = *(const float4*)(x + (size_t)(n0 + xr + 8 * i) * EE + k0 + xc4 * 4);
        }

        // MMA over chunk t
#pragma unroll
        for (int s = 0; s < 4; ++s) {
            const u32 xo = swz((u32)((m0 + (lane & 15)) * 128 + s * 32 + (lane >> 4) * 16));
            u32 a0, a1, a2, a3, f0, f1, f2, f3;
            ldsm4(a0, a1, a2, a3, XH[buf] + xo);
            ldsm4(f0, f1, f2, f3, XL[buf] + xo);
#pragma unroll
            for (int j = 0; j < 4; ++j) {
                const u32 bo_ = swz((u32)((16 * j + (lane & 15)) * 128 + s * 32 + (lane >> 4) * 16));
                u32 h0, h1, h2, h3, l0, l1, l2, l3;
                ldsm4(h0, h1, h2, h3, BH[bslot] + bo_);
                ldsm4(l0, l1, l2, l3, BL[bslot] + bo_);
                mma16816(acc[2 * j],     a0, a1, a2, a3, h0, h2);
                mma16816(acc[2 * j],     a0, a1, a2, a3, l0, l2);
                mma16816(acc[2 * j],     f0, f1, f2, f3, h0, h2);
                mma16816(acc[2 * j + 1], a0, a1, a2, a3, h1, h3);
                mma16816(acc[2 * j + 1], a0, a1, a2, a3, l1, l3);
                mma16816(acc[2 * j + 1], f0, f1, f2, f3, h1, h3);
            }
        }
    }

    // Epilogue: permuted store [F,P]->[P,F], + beta
    const int r0 = lane >> 2;
    const int cb = 2 * (lane & 3);
    const int na = n0 + m0 + r0;
    const int nb2 = na + 8;
    const int pa = na & 1023, ta = na >> 10;
    const int pb2 = nb2 & 1023, tb = nb2 >> 10;
    float* oa = out + (size_t)pa * (FF * CC) + ta * CC;
    float* ob = out + (size_t)pb2 * (FF * CC) + tb * CC;
#pragma unroll
    for (int nt = 0; nt < 8; ++nt) {
        const int c = 8 * nt + cb;
        const float2 b = *(const float2*)&g_beta[c];
        float2 w0, w1;
        w0.x = acc[nt][0] + b.x; w0.y = acc[nt][1] + b.y;
        w1.x = acc[nt][2] + b.x; w1.y = acc[nt][3] + b.y;
        *(float2*)(oa + c) = w0;
        *(float2*)(ob + c) = w1;
    }
}

// ---------------------------------------------------------------------------
extern "C" void kernel_launch(void* const* d_in, const int* in_sizes, int n_in,
                              void* d_out, int out_size)
{
    (void)in_sizes; (void)n_in; (void)out_size;
    const float* emb = (const float*)d_in[0];
    const float* Wv  = (const float*)d_in[3];
    const float* bv  = (const float*)d_in[6];
    const float* Wo  = (const float*)d_in[7];
    const float* bo  = (const float*)d_in[8];
    const float* Wmp = (const float*)d_in[9];
    const float* bmp = (const float*)d_in[10];
    float* out = (float*)d_out;

    const int wg_smem = 65536 + 1024;
    const int mm_smem = 81920 + 1024;
    cudaFuncSetAttribute(wgemm, cudaFuncAttributeMaxDynamicSharedMemorySize, wg_smem);
    cudaFuncSetAttribute(main_mma, cudaFuncAttributeMaxDynamicSharedMemorySize, mm_smem);

    // T1 = Wmp @ Wo (fp32)
    wgemm<<<32, 256, wg_smem>>>(Wmp, Wo, 0, 0, nullptr, nullptr, nullptr, nullptr);
    // M = 0.75 * T1 @ Wv (split bf16 hi/lo, pre-swizzled) + beta in extra block
    wgemm<<<33, 256, wg_smem>>>(nullptr, Wv, 1, 1, bv, bo, bmp, Wmp);

    // Main GEMM (HMMA bf16 3-term split) + permuted epilogue
    main_mma<<<288, 128, mm_smem>>>(emb, out);
}